// round 11
// baseline (speedup 1.0000x reference)
#include <cuda_runtime.h>
#include <cuda.h>
#include <math.h>
#include <stdint.h>

// ---------------- problem constants ----------------
#define TOKENS   8192
#define DMODEL   1024
#define NEXP     8
#define DFFN     2048
#define TOPK     2

#define BM 128
#define BN 64                           // CTA tile N
#define CAP (TOKENS*TOPK + NEXP*BM)    // 17408
#define ROW_TILES (CAP/BM)             // 136

#define BKB 64                          // k bytes (int8 elems) per chunk
#define ROWPITCH 80                     // smem row pitch (conflict-free ldmatrix)
#define APLANE (128*ROWPITCH)           // 10240
#define BPLANE (64*ROWPITCH)            // 5120
#define STAGE_BYTES (2*APLANE + 2*BPLANE)   // 30720
#define NSTAGE 3
#define SMEM_SZ (NSTAGE*STAGE_BYTES + 2048) // 94208 -> 2 CTAs/SM

// ---------------- device scratch ----------------
__device__ __align__(1024) signed char g_xq1[(size_t)CAP * DMODEL];
__device__ __align__(1024) signed char g_xq2[(size_t)CAP * DMODEL];
__device__ __align__(1024) signed char g_hq1[(size_t)CAP * DFFN];
__device__ __align__(1024) signed char g_hq2[(size_t)CAP * DFFN];
__device__ __align__(1024) signed char g_w1q1[(size_t)NEXP * DFFN * DMODEL];
__device__ __align__(1024) signed char g_w1q2[(size_t)NEXP * DFFN * DMODEL];
__device__ __align__(1024) signed char g_w2q1[(size_t)NEXP * DMODEL * DFFN];
__device__ __align__(1024) signed char g_w2q2[(size_t)NEXP * DMODEL * DFFN];
__device__ __align__(1024) float g_hf[(size_t)CAP * DFFN];
__device__ __align__(1024) float g_y[(size_t)CAP * DMODEL];
__device__ float g_sxa[CAP];
__device__ float g_sha[CAP];
__device__ float g_sw1[NEXP * DFFN];
__device__ float g_sw2[NEXP * DMODEL];
__device__ float g_pair_w[CAP];
__device__ int   g_tok2row[TOKENS * TOPK];
__device__ int   g_cnt[NEXP];
__device__ int   g_cursor[NEXP];
__device__ float g_probs[TOKENS * NEXP];
__device__ float g_zsq[TOKENS];
__device__ int   g_sel[TOKENS * TOPK];
__device__ float g_selw[TOKENS * TOPK];

// ---------------- helpers ----------------
__device__ __forceinline__ uint32_t smem_u32(const void* p) {
    uint32_t a;
    asm("{ .reg .u64 t; cvta.to.shared.u64 t, %1; cvt.u32.u64 %0, t; }" : "=r"(a) : "l"(p));
    return a;
}

__device__ __forceinline__ void mma_s8(int* c, const uint32_t* a, const uint32_t* b) {
    asm volatile(
        "mma.sync.aligned.m16n8k32.row.col.s32.s8.s8.s32 "
        "{%0,%1,%2,%3}, {%4,%5,%6,%7}, {%8,%9}, {%0,%1,%2,%3};"
        : "+r"(c[0]), "+r"(c[1]), "+r"(c[2]), "+r"(c[3])
        : "r"(a[0]), "r"(a[1]), "r"(a[2]), "r"(a[3]), "r"(b[0]), "r"(b[1]));
}

__device__ __forceinline__ void ldsm_x4(uint32_t& r0, uint32_t& r1, uint32_t& r2, uint32_t& r3,
                                        uint32_t addr) {
    asm volatile("ldmatrix.sync.aligned.m8n8.x4.shared.b16 {%0,%1,%2,%3}, [%4];"
        : "=r"(r0), "=r"(r1), "=r"(r2), "=r"(r3) : "r"(addr));
}

#define CP_ASYNC16(saddr, gaddr) \
    asm volatile("cp.async.cg.shared.global [%0], [%1], 16;" :: "r"(saddr), "l"(gaddr) : "memory")
#define CP_COMMIT() asm volatile("cp.async.commit_group;" ::: "memory")
#define CP_WAIT1()  asm volatile("cp.async.wait_group 1;" ::: "memory")

__device__ __forceinline__ float gelu_exact(float u) {
    return 0.5f * u * (1.0f + erff(u * 0.70710678118654752440f));
}

__device__ __forceinline__ void quant2(float v, float s, float inv, int& q1, int& q2) {
    float q1f = fminf(fmaxf(rintf(v * inv), -127.f), 127.f);
    float q2f = fminf(fmaxf(rintf((v - q1f * s) * inv * 128.f), -127.f), 127.f);
    q1 = (int)q1f; q2 = (int)q2f;
}

__device__ __forceinline__ void calc_off(int* off) {
    int o = 0;
#pragma unroll
    for (int e = 0; e < NEXP; e++) {
        off[e] = o;
        o += ((g_cnt[e] + BM - 1) / BM) * BM;
    }
    off[NEXP] = o;
}

// ---------------- router: warp per token ----------------
__global__ __launch_bounds__(256) void router_kernel(const float* __restrict__ x,
                                                     const float* __restrict__ rw) {
    __shared__ float srw[NEXP * DMODEL];
    int tid = threadIdx.x;
    for (int i = tid; i < NEXP * DMODEL; i += 256) srw[i] = rw[i];
    __syncthreads();

    int warp = tid >> 5, lane = tid & 31;
    int tok = blockIdx.x * 8 + warp;
    if (tok >= TOKENS) return;

    const float* xr = x + (size_t)tok * DMODEL;
    float acc[NEXP];
#pragma unroll
    for (int e = 0; e < NEXP; e++) acc[e] = 0.f;
    for (int i = lane; i < DMODEL; i += 32) {
        float xv = xr[i];
#pragma unroll
        for (int e = 0; e < NEXP; e++) acc[e] += xv * srw[e * DMODEL + i];
    }
#pragma unroll
    for (int off = 16; off; off >>= 1)
#pragma unroll
        for (int e = 0; e < NEXP; e++)
            acc[e] += __shfl_down_sync(0xffffffffu, acc[e], off);

    if (lane == 0) {
        float m = acc[0];
#pragma unroll
        for (int e = 1; e < NEXP; e++) m = fmaxf(m, acc[e]);
        float p[NEXP], s = 0.f;
#pragma unroll
        for (int e = 0; e < NEXP; e++) { p[e] = expf(acc[e] - m); s += p[e]; }
        float inv = 1.f / s;
#pragma unroll
        for (int e = 0; e < NEXP; e++) { p[e] *= inv; g_probs[tok * NEXP + e] = p[e]; }
        float lse = logf(s) + m;
        g_zsq[tok] = lse * lse;

        int e1 = 0;
#pragma unroll
        for (int e = 1; e < NEXP; e++) if (p[e] > p[e1]) e1 = e;
        int e2 = (e1 == 0) ? 1 : 0;
#pragma unroll
        for (int e = 0; e < NEXP; e++) if (e != e1 && p[e] > p[e2]) e2 = e;

        float wsum = p[e1] + p[e2];
        g_sel[tok * 2 + 0] = e1;  g_selw[tok * 2 + 0] = p[e1] / wsum;
        g_sel[tok * 2 + 1] = e2;  g_selw[tok * 2 + 1] = p[e2] / wsum;
        atomicAdd(&g_cnt[e1], 1);
        atomicAdd(&g_cnt[e2], 1);
    }
}

// ---------------- fused scatter + gather + int8x2 quantize (x rows) ----------------
__global__ __launch_bounds__(128) void scatter_gather(const float* __restrict__ x) {
    __shared__ int spos[2];
    __shared__ float sred[128];
    int t = blockIdx.x;
    int tid = threadIdx.x;
    if (tid == 0) {
        int off[NEXP + 1];
        calc_off(off);
#pragma unroll
        for (int k = 0; k < TOPK; k++) {
            int e = g_sel[t * 2 + k];
            int pos = off[e] + atomicAdd(&g_cursor[e], 1);
            g_pair_w[pos] = g_selw[t * 2 + k];
            g_tok2row[t * 2 + k] = pos;
            spos[k] = pos;
        }
    }
    __syncthreads();
    int p0 = spos[0], p1 = spos[1];

    const float4* src = (const float4*)(x + (size_t)t * DMODEL);
    float4 v[2];
    float m = 0.f;
#pragma unroll
    for (int i = 0; i < 2; i++) {
        v[i] = src[tid + 128 * i];
        m = fmaxf(m, fmaxf(fmaxf(fabsf(v[i].x), fabsf(v[i].y)),
                           fmaxf(fabsf(v[i].z), fabsf(v[i].w))));
    }
    sred[tid] = m; __syncthreads();
    for (int s = 64; s; s >>= 1) { if (tid < s) sred[tid] = fmaxf(sred[tid], sred[tid + s]); __syncthreads(); }
    float rm = fmaxf(sred[0], 1e-20f);
    float sc = rm / 127.f, inv = 127.f / rm;
    if (tid == 0) { g_sxa[p0] = sc; g_sxa[p1] = sc; }

#pragma unroll
    for (int i = 0; i < 2; i++) {
        int q1[4], q2[4];
        quant2(v[i].x, sc, inv, q1[0], q2[0]);
        quant2(v[i].y, sc, inv, q1[1], q2[1]);
        quant2(v[i].z, sc, inv, q1[2], q2[2]);
        quant2(v[i].w, sc, inv, q1[3], q2[3]);
        char4 c1 = make_char4((char)q1[0], (char)q1[1], (char)q1[2], (char)q1[3]);
        char4 c2 = make_char4((char)q2[0], (char)q2[1], (char)q2[2], (char)q2[3]);
        int idx = tid + 128 * i;
        ((char4*)(g_xq1 + (size_t)p0 * DMODEL))[idx] = c1;
        ((char4*)(g_xq2 + (size_t)p0 * DMODEL))[idx] = c2;
        ((char4*)(g_xq1 + (size_t)p1 * DMODEL))[idx] = c1;
        ((char4*)(g_xq2 + (size_t)p1 * DMODEL))[idx] = c2;
    }
}

// ---------------- w1: per-column max + transpose + quantize ----------------
// w1 [k=1024][c=16384]  ->  q planes [c][k], scale g_sw1[c]
__global__ void w1_quant(const float* __restrict__ in) {
    __shared__ float red[8][32];
    __shared__ float ss[32], sinv[32];
    __shared__ float tile[32][33];
    int tx = threadIdx.x, ty = threadIdx.y;
    int c0 = blockIdx.x * 32;

    float m = 0.f;
    for (int k = ty; k < DMODEL; k += 8)
        m = fmaxf(m, fabsf(in[(size_t)k * 16384 + c0 + tx]));
    red[ty][tx] = m; __syncthreads();
    if (ty == 0) {
        float mm = red[0][tx];
#pragma unroll
        for (int i = 1; i < 8; i++) mm = fmaxf(mm, red[i][tx]);
        mm = fmaxf(mm, 1e-20f);
        ss[tx] = mm / 127.f; sinv[tx] = 127.f / mm;
        g_sw1[c0 + tx] = mm / 127.f;
    }
    __syncthreads();

    int tid = ty * 32 + tx;
    int rowl = tid >> 3, quad = tid & 7;
    for (int k0 = 0; k0 < DMODEL; k0 += 32) {
#pragma unroll
        for (int i = 0; i < 4; i++)
            tile[ty + 8 * i][tx] = in[(size_t)(k0 + ty + 8 * i) * 16384 + c0 + tx];
        __syncthreads();
        float sc = ss[rowl], inv = sinv[rowl];
        int q1[4], q2[4];
#pragma unroll
        for (int qi = 0; qi < 4; qi++)
            quant2(tile[quad * 4 + qi][rowl], sc, inv, q1[qi], q2[qi]);
        size_t base = (size_t)(c0 + rowl) * DMODEL + k0 + quad * 4;
        *(char4*)(g_w1q1 + base) = make_char4((char)q1[0], (char)q1[1], (char)q1[2], (char)q1[3]);
        *(char4*)(g_w1q2 + base) = make_char4((char)q2[0], (char)q2[1], (char)q2[2], (char)q2[3]);
        __syncthreads();
    }
}

// ---------------- w2: per-column max + transpose + quantize ----------------
// w2 [e][k=2048][n=1024] -> q planes [(e,n)][k], scale g_sw2[e*1024+n]
__global__ void w2_quant(const float* __restrict__ in) {
    __shared__ float red[8][32];
    __shared__ float ss[32], sinv[32];
    __shared__ float tile[32][33];
    int tx = threadIdx.x, ty = threadIdx.y;
    int n0 = blockIdx.x * 32;
    int e  = blockIdx.y;
    const float* src = in + (size_t)e * DFFN * DMODEL;

    float m = 0.f;
    for (int k = ty; k < DFFN; k += 8)
        m = fmaxf(m, fabsf(src[(size_t)k * DMODEL + n0 + tx]));
    red[ty][tx] = m; __syncthreads();
    if (ty == 0) {
        float mm = red[0][tx];
#pragma unroll
        for (int i = 1; i < 8; i++) mm = fmaxf(mm, red[i][tx]);
        mm = fmaxf(mm, 1e-20f);
        ss[tx] = mm / 127.f; sinv[tx] = 127.f / mm;
        g_sw2[e * DMODEL + n0 + tx] = mm / 127.f;
    }
    __syncthreads();

    int tid = ty * 32 + tx;
    int rowl = tid >> 3, quad = tid & 7;
    for (int k0 = 0; k0 < DFFN; k0 += 32) {
#pragma unroll
        for (int i = 0; i < 4; i++)
            tile[ty + 8 * i][tx] = src[(size_t)(k0 + ty + 8 * i) * DMODEL + n0 + tx];
        __syncthreads();
        float sc = ss[rowl], inv = sinv[rowl];
        int q1[4], q2[4];
#pragma unroll
        for (int qi = 0; qi < 4; qi++)
            quant2(tile[quad * 4 + qi][rowl], sc, inv, q1[qi], q2[qi]);
        size_t base = ((size_t)e * DMODEL + n0 + rowl) * DFFN + k0 + quad * 4;
        *(char4*)(g_w2q1 + base) = make_char4((char)q1[0], (char)q1[1], (char)q1[2], (char)q1[3]);
        *(char4*)(g_w2q2 + base) = make_char4((char)q2[0], (char)q2[1], (char)q2[2], (char)q2[3]);
        __syncthreads();
    }
}

// ---------------- h: per-row max + quantize ----------------
__global__ __launch_bounds__(256) void h_quant() {
    __shared__ float sred[256];
    int row = blockIdx.x, tid = threadIdx.x;
    const float4* src = (const float4*)(g_hf + (size_t)row * DFFN);
    float4 v[2];
    float m = 0.f;
#pragma unroll
    for (int i = 0; i < 2; i++) {
        v[i] = src[tid + 256 * i];
        m = fmaxf(m, fmaxf(fmaxf(fabsf(v[i].x), fabsf(v[i].y)),
                           fmaxf(fabsf(v[i].z), fabsf(v[i].w))));
    }
    sred[tid] = m; __syncthreads();
    for (int s = 128; s; s >>= 1) { if (tid < s) sred[tid] = fmaxf(sred[tid], sred[tid + s]); __syncthreads(); }
    float rm = fmaxf(sred[0], 1e-20f);
    float sc = rm / 127.f, inv = 127.f / rm;
    if (tid == 0) g_sha[row] = sc;

#pragma unroll
    for (int i = 0; i < 2; i++) {
        int q1[4], q2[4];
        quant2(v[i].x, sc, inv, q1[0], q2[0]);
        quant2(v[i].y, sc, inv, q1[1], q2[1]);
        quant2(v[i].z, sc, inv, q1[2], q2[2]);
        quant2(v[i].w, sc, inv, q1[3], q2[3]);
        int idx = tid + 256 * i;
        ((char4*)(g_hq1 + (size_t)row * DFFN))[idx] =
            make_char4((char)q1[0], (char)q1[1], (char)q1[2], (char)q1[3]);
        ((char4*)(g_hq2 + (size_t)row * DFFN))[idx] =
            make_char4((char)q2[0], (char)q2[1], (char)q2[2], (char)q2[3]);
    }
}

// ===== GEMM: int8x2 IMMA, 128x64 CTA tile, 256 thr, 2 CTAs/SM, warp tile 32x32 =====
template <bool FFN1>
__global__ __launch_bounds__(256, 2) void gemm_s8(const signed char* __restrict__ Aq1,
                                                  const signed char* __restrict__ Aq2,
                                                  const signed char* __restrict__ Bq1,
                                                  const signed char* __restrict__ Bq2,
                                                  const float* __restrict__ sa,
                                                  const float* __restrict__ sb) {
    const int KDIM = FFN1 ? DMODEL : DFFN;   // bytes per row
    const int NCH  = KDIM / BKB;

    int off[NEXP + 1];
    calc_off(off);

    int row0 = blockIdx.y * BM;
    if (row0 >= off[NEXP]) return;
    int e = 0;
#pragma unroll
    for (int i = 0; i < NEXP; i++) if (row0 >= off[i + 1]) e = i + 1;

    const int n0 = blockIdx.x * BN;
    const int ybase = (FFN1 ? e * DFFN : e * DMODEL) + n0;
    int tid = threadIdx.x, wid = tid >> 5, lane = tid & 31;
    int wr = wid >> 1, wc = wid & 1;            // 4x2 warp grid; warp tile 32x32
    int gid = lane >> 2, tig = lane & 3;

    extern __shared__ char smem[];
    uint32_t sbase = smem_u32(smem);
    float* aux = (float*)(smem + NSTAGE * STAGE_BYTES);
    float* swt = aux;          // [128]
    float* ssa = aux + 128;    // [128]
    float* ssb = aux + 256;    // [64]
    if (tid < BM) ssa[tid] = sa[row0 + tid];
    if (tid < BN) ssb[tid] = sb[ybase + tid];
    if (!FFN1 && tid < BM) swt[tid] = g_pair_w[row0 + tid];

    int sel = lane >> 3, lr = lane & 7;
    uint32_t aoff = (uint32_t)((wr * 32 + (sel & 1) * 8 + lr) * ROWPITCH + (sel >> 1) * 16);
    uint32_t boff = (uint32_t)((wc * 32 + (sel >> 1) * 8 + lr) * ROWPITCH + (sel & 1) * 16);

    int c1[2][4][4], c2[2][4][4];
#pragma unroll
    for (int i = 0; i < 2; i++)
#pragma unroll
        for (int j = 0; j < 4; j++)
#pragma unroll
            for (int q = 0; q < 4; q++) { c1[i][j][q] = 0; c2[i][j][q] = 0; }

    // stage fill: 1536 x 16B per stage, 6 per thread
    auto fill = [&](int st, int kc) {
        uint32_t base = sbase + st * STAGE_BYTES;
        int k0 = kc * BKB;
#pragma unroll
        for (int it = 0; it < 6; it++) {
            int q = tid + 256 * it;
            if (q < 1024) {                       // A planes: 2 x (128 rows x 4)
                int plane = q >> 9;
                int rr = (q >> 2) & 127;
                int cc = q & 3;
                uint32_t dst = base + plane * APLANE + rr * ROWPITCH + cc * 16;
                const signed char* src = (plane ? Aq2 : Aq1)
                    + (size_t)(row0 + rr) * KDIM + k0 + cc * 16;
                CP_ASYNC16(dst, src);
            } else {                              // B planes: 2 x (64 rows x 4)
                int qq = q - 1024;
                int plane = qq >> 8;
                int rr = (qq >> 2) & 63;
                int cc = qq & 3;
                uint32_t dst = base + 2 * APLANE + plane * BPLANE + rr * ROWPITCH + cc * 16;
                const signed char* src = (plane ? Bq2 : Bq1)
                    + (size_t)(ybase + rr) * KDIM + k0 + cc * 16;
                CP_ASYNC16(dst, src);
            }
        }
    };

    fill(0, 0); CP_COMMIT();
    fill(1, 1); CP_COMMIT();

    for (int kc = 0; kc < NCH; kc++) {
        CP_WAIT1();
        __syncthreads();
        if (kc + 2 < NCH) { fill((kc + 2) % NSTAGE, kc + 2); }
        CP_COMMIT();

        uint32_t stg = sbase + (kc % NSTAGE) * STAGE_BYTES;
#pragma unroll
        for (int kk = 0; kk < 2; kk++) {
            uint32_t a1[2][4], a2[2][4], b1[4][2], b2[4][2];
#pragma unroll
            for (int i = 0; i < 2; i++) {
                uint32_t a_addr = stg + i * (16 * ROWPITCH) + kk * 32 + aoff;
                ldsm_x4(a1[i][0], a1[i][1], a1[i][2], a1[i][3], a_addr);
                ldsm_x4(a2[i][0], a2[i][1], a2[i][2], a2[i][3], a_addr + APLANE);
            }
#pragma unroll
            for (int jp = 0; jp < 2; jp++) {
                uint32_t b_addr = stg + 2 * APLANE + jp * (16 * ROWPITCH) + kk * 32 + boff;
                ldsm_x4(b1[jp * 2][0], b1[jp * 2][1], b1[jp * 2 + 1][0], b1[jp * 2 + 1][1], b_addr);
                ldsm_x4(b2[jp * 2][0], b2[jp * 2][1], b2[jp * 2 + 1][0], b2[jp * 2 + 1][1],
                        b_addr + BPLANE);
            }
            // pass1: q1*p1 -> c1 ; pass2: q1*p2 and q2*p1 -> c2 (shared scale /128)
#pragma unroll
            for (int i = 0; i < 2; i++)
#pragma unroll
                for (int j = 0; j < 4; j++) mma_s8(c1[i][j], a1[i], b1[j]);
#pragma unroll
            for (int i = 0; i < 2; i++)
#pragma unroll
                for (int j = 0; j < 4; j++) mma_s8(c2[i][j], a1[i], b2[j]);
#pragma unroll
            for (int i = 0; i < 2; i++)
#pragma unroll
                for (int j = 0; j < 4; j++) mma_s8(c2[i][j], a2[i], b1[j]);
        }
        __syncthreads();
    }

    // epilogue: dequant + (gelu->g_hf | weighted->g_y)
#pragma unroll
    for (int i = 0; i < 2; i++) {
        int mr0 = wr * 32 + i * 16 + gid;
        int mr1 = mr0 + 8;
        float sa0 = ssa[mr0], sa1 = ssa[mr1];
#pragma unroll
        for (int j = 0; j < 4; j++) {
            int col = wc * 32 + j * 8 + tig * 2;
            float sb0 = ssb[col], sb1 = ssb[col + 1];
            float v00 = sa0 * sb0 * ((float)c1[i][j][0] + (float)c2[i][j][0] * 0.0078125f);
            float v01 = sa0 * sb1 * ((float)c1[i][j][1] + (float)c2[i][j][1] * 0.0078125f);
            float v10 = sa1 * sb0 * ((float)c1[i][j][2] + (float)c2[i][j][2] * 0.0078125f);
            float v11 = sa1 * sb1 * ((float)c1[i][j][3] + (float)c2[i][j][3] * 0.0078125f);
            if (FFN1) {
                float* h0 = g_hf + (size_t)(row0 + mr0) * DFFN + n0 + col;
                float* h1 = g_hf + (size_t)(row0 + mr1) * DFFN + n0 + col;
                *(float2*)h0 = make_float2(gelu_exact(v00), gelu_exact(v01));
                *(float2*)h1 = make_float2(gelu_exact(v10), gelu_exact(v11));
            } else {
                float ws0 = swt[mr0], ws1 = swt[mr1];
                float* y0 = g_y + (size_t)(row0 + mr0) * DMODEL + n0 + col;
                float* y1 = g_y + (size_t)(row0 + mr1) * DMODEL + n0 + col;
                *(float2*)y0 = make_float2(ws0 * v00, ws0 * v01);
                *(float2*)y1 = make_float2(ws1 * v10, ws1 * v11);
            }
        }
    }
}

// ---------------- combine ----------------
__global__ __launch_bounds__(128) void combine_kernel(float* __restrict__ out) {
    int t = blockIdx.x;
    int ra = g_tok2row[t * 2 + 0];
    int rb = g_tok2row[t * 2 + 1];
    const float4* ya = (const float4*)(g_y + (size_t)ra * DMODEL);
    const float4* yb = (const float4*)(g_y + (size_t)rb * DMODEL);
    float4* o = (float4*)(out + (size_t)t * DMODEL);
    for (int i = threadIdx.x; i < DMODEL / 4; i += 128) {
        float4 a = ya[i], b = yb[i];
        o[i] = make_float4(a.x + b.x, a.y + b.y, a.z + b.z, a.w + b.w);
    }
}

// ---------------- aux losses ----------------
__global__ __launch_bounds__(256) void reduce_kernel(float* __restrict__ out, int out_size) {
    __shared__ float sbuf[256];
    int tid = threadIdx.x;

    float z = 0.f;
    for (int t = tid; t < TOKENS; t += 256) z += g_zsq[t];
    sbuf[tid] = z; __syncthreads();
    for (int s = 128; s; s >>= 1) { if (tid < s) sbuf[tid] += sbuf[tid + s]; __syncthreads(); }
    float zloss = sbuf[0] / (float)TOKENS;
    __syncthreads();

    float p[NEXP];
#pragma unroll
    for (int e = 0; e < NEXP; e++) p[e] = 0.f;
    for (int t = tid; t < TOKENS; t += 256) {
#pragma unroll
        for (int e = 0; e < NEXP; e++) p[e] += g_probs[t * NEXP + e];
    }
    float pi[NEXP];
#pragma unroll
    for (int e = 0; e < NEXP; e++) {
        sbuf[tid] = p[e]; __syncthreads();
        for (int s = 128; s; s >>= 1) { if (tid < s) sbuf[tid] += sbuf[tid + s]; __syncthreads(); }
        pi[e] = sbuf[0] / (float)TOKENS;
        __syncthreads();
    }

    if (tid == 0 && out_size >= TOKENS * DMODEL + 2 + NEXP) {
        float* tail = out + (size_t)TOKENS * DMODEL;
        tail[0] = zloss;
        float lb = 0.f;
#pragma unroll
        for (int e = 0; e < NEXP; e++) {
            float fi = (float)g_cnt[e] / (float)(TOKENS * TOPK);
            lb += fi * pi[e];
            tail[2 + e] = fi;
        }
        tail[1] = (float)NEXP * lb;
    }
}

// ---------------- host ----------------
extern "C" void kernel_launch(void* const* d_in, const int* in_sizes, int n_in,
                              void* d_out, int out_size) {
    const float* x  = (const float*)d_in[0];
    const float* rw = (const float*)d_in[1];
    const float* w1 = (const float*)d_in[2];
    const float* w2 = (const float*)d_in[3];
    float* out = (float*)d_out;

    void *p_cnt, *p_cur;
    void *p_xq1, *p_xq2, *p_hq1, *p_hq2, *p_w1q1, *p_w1q2, *p_w2q1, *p_w2q2;
    void *p_sxa, *p_sha, *p_sw1, *p_sw2;
    cudaGetSymbolAddress(&p_cnt, g_cnt);
    cudaGetSymbolAddress(&p_cur, g_cursor);
    cudaGetSymbolAddress(&p_xq1, g_xq1);   cudaGetSymbolAddress(&p_xq2, g_xq2);
    cudaGetSymbolAddress(&p_hq1, g_hq1);   cudaGetSymbolAddress(&p_hq2, g_hq2);
    cudaGetSymbolAddress(&p_w1q1, g_w1q1); cudaGetSymbolAddress(&p_w1q2, g_w1q2);
    cudaGetSymbolAddress(&p_w2q1, g_w2q1); cudaGetSymbolAddress(&p_w2q2, g_w2q2);
    cudaGetSymbolAddress(&p_sxa, g_sxa);   cudaGetSymbolAddress(&p_sha, g_sha);
    cudaGetSymbolAddress(&p_sw1, g_sw1);   cudaGetSymbolAddress(&p_sw2, g_sw2);

    cudaFuncSetAttribute(gemm_s8<true>,  cudaFuncAttributeMaxDynamicSharedMemorySize, SMEM_SZ);
    cudaFuncSetAttribute(gemm_s8<false>, cudaFuncAttributeMaxDynamicSharedMemorySize, SMEM_SZ);

    cudaMemsetAsync(p_cnt, 0, NEXP * sizeof(int));
    cudaMemsetAsync(p_cur, 0, NEXP * sizeof(int));

    // k1..k3 feed gemm1 (k4 = ncu capture slot)
    router_kernel<<<TOKENS / 8, 256>>>(x, rw);                              // k1
    scatter_gather<<<TOKENS, 128>>>(x);                                     // k2
    w1_quant<<<16384 / 32, dim3(32, 8)>>>(w1);                              // k3

    gemm_s8<true><<<dim3(DFFN / BN, ROW_TILES), 256, SMEM_SZ>>>(            // k4 <- profiled
        (const signed char*)p_xq1, (const signed char*)p_xq2,
        (const signed char*)p_w1q1, (const signed char*)p_w1q2,
        (const float*)p_sxa, (const float*)p_sw1);

    w2_quant<<<dim3(DMODEL / 32, NEXP), dim3(32, 8)>>>(w2);                 // k5
    h_quant<<<CAP, 256>>>();                                                // k6

    gemm_s8<false><<<dim3(DMODEL / BN, ROW_TILES), 256, SMEM_SZ>>>(         // k7
        (const signed char*)p_hq1, (const signed char*)p_hq2,
        (const signed char*)p_w2q1, (const signed char*)p_w2q2,
        (const float*)p_sha, (const float*)p_sw2);

    combine_kernel<<<TOKENS, 128>>>(out);                                   // k8
    reduce_kernel<<<1, 256>>>(out, out_size);                               // k9
}

// round 12
// speedup vs baseline: 2.6944x; 2.6944x over previous
#include <cuda_runtime.h>
#include <cuda.h>
#include <cuda_bf16.h>
#include <math.h>
#include <stdint.h>

// ---------------- problem constants ----------------
#define TOKENS   8192
#define DMODEL   1024
#define NEXP     8
#define DFFN     2048
#define TOPK     2

#define BM 128
#define BN 128                          // CTA tile N
#define CAP (TOKENS*TOPK + NEXP*BM)    // 17408
#define ROW_TILES (CAP/BM)             // 136

#define BK 32                           // k elements per stage chunk
#define APLANE 8192                     // 128 rows x 64B (swizzled, no padding)
#define BPLANE 8192
#define STAGE_BYTES (2*APLANE + 2*BPLANE)   // 32768
#define NSTAGE 3
#define SMEM_SZ (NSTAGE*STAGE_BYTES + 512)  // 98816 -> 2 CTAs/SM

// ---------------- device scratch (bf16 hi/lo planes) ----------------
__device__ __align__(1024) __nv_bfloat16 g_xg_hi[(size_t)CAP * DMODEL];
__device__ __align__(1024) __nv_bfloat16 g_xg_lo[(size_t)CAP * DMODEL];
__device__ __align__(1024) __nv_bfloat16 g_h_hi[(size_t)CAP * DFFN];
__device__ __align__(1024) __nv_bfloat16 g_h_lo[(size_t)CAP * DFFN];
__device__ __align__(1024) __nv_bfloat16 g_w1t_hi[(size_t)NEXP * DFFN * DMODEL];
__device__ __align__(1024) __nv_bfloat16 g_w1t_lo[(size_t)NEXP * DFFN * DMODEL];
__device__ __align__(1024) __nv_bfloat16 g_w2t_hi[(size_t)NEXP * DMODEL * DFFN];
__device__ __align__(1024) __nv_bfloat16 g_w2t_lo[(size_t)NEXP * DMODEL * DFFN];
__device__ __align__(1024) float g_y[(size_t)CAP * DMODEL];
__device__ float g_pair_w[CAP];
__device__ int   g_tok2row[TOKENS * TOPK];
__device__ int   g_cnt[NEXP];
__device__ int   g_cursor[NEXP];
__device__ float g_probs[TOKENS * NEXP];
__device__ float g_zsq[TOKENS];
__device__ int   g_sel[TOKENS * TOPK];
__device__ float g_selw[TOKENS * TOPK];

// ---------------- helpers ----------------
__device__ __forceinline__ uint32_t smem_u32(const void* p) {
    uint32_t a;
    asm("{ .reg .u64 t; cvta.to.shared.u64 t, %1; cvt.u32.u64 %0, t; }" : "=r"(a) : "l"(p));
    return a;
}

__device__ __forceinline__ void mma_bf16(float* c, const uint32_t* a, const uint32_t* b) {
    asm volatile(
        "mma.sync.aligned.m16n8k16.row.col.f32.bf16.bf16.f32 "
        "{%0,%1,%2,%3}, {%4,%5,%6,%7}, {%8,%9}, {%0,%1,%2,%3};"
        : "+f"(c[0]), "+f"(c[1]), "+f"(c[2]), "+f"(c[3])
        : "r"(a[0]), "r"(a[1]), "r"(a[2]), "r"(a[3]), "r"(b[0]), "r"(b[1]));
}

__device__ __forceinline__ void ldsm_x4(uint32_t& r0, uint32_t& r1, uint32_t& r2, uint32_t& r3,
                                        uint32_t addr) {
    asm volatile("ldmatrix.sync.aligned.m8n8.x4.shared.b16 {%0,%1,%2,%3}, [%4];"
        : "=r"(r0), "=r"(r1), "=r"(r2), "=r"(r3) : "r"(addr));
}

#define CP_ASYNC16(saddr, gaddr) \
    asm volatile("cp.async.cg.shared.global [%0], [%1], 16;" :: "r"(saddr), "l"(gaddr) : "memory")
#define CP_COMMIT() asm volatile("cp.async.commit_group;" ::: "memory")
#define CP_WAIT1()  asm volatile("cp.async.wait_group 1;" ::: "memory")

__device__ __forceinline__ float gelu_exact(float u) {
    return 0.5f * u * (1.0f + erff(u * 0.70710678118654752440f));
}

__device__ __forceinline__ void calc_off(int* off) {
    int o = 0;
#pragma unroll
    for (int e = 0; e < NEXP; e++) {
        off[e] = o;
        o += ((g_cnt[e] + BM - 1) / BM) * BM;
    }
    off[NEXP] = o;
}

// ---------------- router: warp per token ----------------
__global__ __launch_bounds__(256) void router_kernel(const float* __restrict__ x,
                                                     const float* __restrict__ rw) {
    __shared__ float srw[NEXP * DMODEL];
    int tid = threadIdx.x;
    for (int i = tid; i < NEXP * DMODEL; i += 256) srw[i] = rw[i];
    __syncthreads();

    int warp = tid >> 5, lane = tid & 31;
    int tok = blockIdx.x * 8 + warp;
    if (tok >= TOKENS) return;

    const float* xr = x + (size_t)tok * DMODEL;
    float acc[NEXP];
#pragma unroll
    for (int e = 0; e < NEXP; e++) acc[e] = 0.f;
    for (int i = lane; i < DMODEL; i += 32) {
        float xv = xr[i];
#pragma unroll
        for (int e = 0; e < NEXP; e++) acc[e] += xv * srw[e * DMODEL + i];
    }
#pragma unroll
    for (int off = 16; off; off >>= 1)
#pragma unroll
        for (int e = 0; e < NEXP; e++)
            acc[e] += __shfl_down_sync(0xffffffffu, acc[e], off);

    if (lane == 0) {
        float m = acc[0];
#pragma unroll
        for (int e = 1; e < NEXP; e++) m = fmaxf(m, acc[e]);
        float p[NEXP], s = 0.f;
#pragma unroll
        for (int e = 0; e < NEXP; e++) { p[e] = expf(acc[e] - m); s += p[e]; }
        float inv = 1.f / s;
#pragma unroll
        for (int e = 0; e < NEXP; e++) { p[e] *= inv; g_probs[tok * NEXP + e] = p[e]; }
        float lse = logf(s) + m;
        g_zsq[tok] = lse * lse;

        int e1 = 0;
#pragma unroll
        for (int e = 1; e < NEXP; e++) if (p[e] > p[e1]) e1 = e;
        int e2 = (e1 == 0) ? 1 : 0;
#pragma unroll
        for (int e = 0; e < NEXP; e++) if (e != e1 && p[e] > p[e2]) e2 = e;

        float wsum = p[e1] + p[e2];
        g_sel[tok * 2 + 0] = e1;  g_selw[tok * 2 + 0] = p[e1] / wsum;
        g_sel[tok * 2 + 1] = e2;  g_selw[tok * 2 + 1] = p[e2] / wsum;
        atomicAdd(&g_cnt[e1], 1);
        atomicAdd(&g_cnt[e2], 1);
    }
}

// fused scatter + gather/split: block per token
__global__ __launch_bounds__(128) void scatter_gather(const float* __restrict__ x) {
    __shared__ int spos[2];
    int t = blockIdx.x;
    if (threadIdx.x == 0) {
        int off[NEXP + 1];
        calc_off(off);
#pragma unroll
        for (int k = 0; k < TOPK; k++) {
            int e = g_sel[t * 2 + k];
            int pos = off[e] + atomicAdd(&g_cursor[e], 1);
            g_pair_w[pos] = g_selw[t * 2 + k];
            g_tok2row[t * 2 + k] = pos;
            spos[k] = pos;
        }
    }
    __syncthreads();
    int p0 = spos[0], p1 = spos[1];
    const float2* src = (const float2*)(x + (size_t)t * DMODEL);
    __nv_bfloat162* dh0 = (__nv_bfloat162*)(g_xg_hi + (size_t)p0 * DMODEL);
    __nv_bfloat162* dl0 = (__nv_bfloat162*)(g_xg_lo + (size_t)p0 * DMODEL);
    __nv_bfloat162* dh1 = (__nv_bfloat162*)(g_xg_hi + (size_t)p1 * DMODEL);
    __nv_bfloat162* dl1 = (__nv_bfloat162*)(g_xg_lo + (size_t)p1 * DMODEL);
    for (int i = threadIdx.x; i < DMODEL / 2; i += 128) {
        float2 v = src[i];
        __nv_bfloat162 h = __floats2bfloat162_rn(v.x, v.y);
        float2 hf = __bfloat1622float2(h);
        __nv_bfloat162 l = __floats2bfloat162_rn(v.x - hf.x, v.y - hf.y);
        dh0[i] = h; dl0[i] = l;
        dh1[i] = h; dl1[i] = l;
    }
}

// w1 [1024][16384] -> planes [(e,n)][k]
__global__ __launch_bounds__(256) void transpose_w1_split(const float* __restrict__ in) {
    __shared__ float t[32][33];
    int c0 = blockIdx.x * 32, r0 = blockIdx.y * 32;
    int x = threadIdx.x, y = threadIdx.y;
#pragma unroll
    for (int i = 0; i < 32; i += 8) t[y + i][x] = in[(size_t)(r0 + y + i) * 16384 + c0 + x];
    __syncthreads();
#pragma unroll
    for (int i = 0; i < 32; i += 8) {
        float v = t[x][y + i];
        size_t idx = (size_t)(c0 + y + i) * 1024 + r0 + x;
        __nv_bfloat16 h = __float2bfloat16(v);
        g_w1t_hi[idx] = h;
        g_w1t_lo[idx] = __float2bfloat16(v - __bfloat162float(h));
    }
}

// w2 [e][2048][1024] -> planes [(e,n)][k]
__global__ __launch_bounds__(256) void transpose_w2_split(const float* __restrict__ in) {
    __shared__ float t[32][33];
    int e = blockIdx.z;
    int n0 = blockIdx.x * 32, k0 = blockIdx.y * 32;
    int x = threadIdx.x, y = threadIdx.y;
#pragma unroll
    for (int i = 0; i < 32; i += 8)
        t[y + i][x] = in[((size_t)e * 2048 + k0 + y + i) * 1024 + n0 + x];
    __syncthreads();
#pragma unroll
    for (int i = 0; i < 32; i += 8) {
        float v = t[x][y + i];
        size_t idx = ((size_t)e * 1024 + n0 + y + i) * 2048 + k0 + x;
        __nv_bfloat16 h = __float2bfloat16(v);
        g_w2t_hi[idx] = h;
        g_w2t_lo[idx] = __float2bfloat16(v - __bfloat162float(h));
    }
}

// ===== GEMM: 128x128 tile, 256 thr, 2 CTAs/SM, 3-stage swizzled smem, 1 bar/chunk =====
// smem plane layout: row r (64B), 16B chunk c stored at  r*64 + ((c ^ ((r>>1)&3))<<4)
template <bool FFN1>
__global__ __launch_bounds__(256, 2) void gemm_bf16(const __nv_bfloat16* __restrict__ Ah,
                                                    const __nv_bfloat16* __restrict__ Al,
                                                    const __nv_bfloat16* __restrict__ Bh,
                                                    const __nv_bfloat16* __restrict__ Bl) {
    const int KDIM = FFN1 ? DMODEL : DFFN;
    const int NCH  = KDIM / BK;

    int off[NEXP + 1];
    calc_off(off);

    int row0 = blockIdx.y * BM;
    if (row0 >= off[NEXP]) return;
    int e = 0;
#pragma unroll
    for (int i = 0; i < NEXP; i++) if (row0 >= off[i + 1]) e = i + 1;

    const int n0 = blockIdx.x * BN;
    const int ybase = (FFN1 ? e * DFFN : e * DMODEL) + n0;
    int tid = threadIdx.x, wid = tid >> 5, lane = tid & 31;
    int wr = wid >> 2, wc = wid & 3;            // 2x4 warp grid; warp tile 64x32
    int gid = lane >> 2, tig = lane & 3;

    extern __shared__ char smem[];
    uint32_t sbase = smem_u32(smem);
    float* swt = (float*)(smem + NSTAGE * STAGE_BYTES);
    if (!FFN1 && tid < BM) swt[tid] = g_pair_w[row0 + tid];

    // ldmatrix lane addressing with XOR swizzle (swizzle term invariant in i/jp: +16 rows)
    int sel = lane >> 3, lr = lane & 7;
    int ra0 = wr * 64 + (sel & 1) * 8 + lr;
    int rb0 = wc * 32 + (sel >> 1) * 8 + lr;
    int xa = (sel >> 1) ^ ((ra0 >> 1) & 3);     // base chunk (kk=0)
    int xb = (sel & 1)  ^ ((rb0 >> 1) & 3);
    uint32_t abase = (uint32_t)(ra0 * 64);
    uint32_t bbase = (uint32_t)(rb0 * 64);

    float c[4][4][4];
#pragma unroll
    for (int i = 0; i < 4; i++)
#pragma unroll
        for (int j = 0; j < 4; j++)
#pragma unroll
            for (int q = 0; q < 4; q++) c[i][j][q] = 0.f;

    // stage fill: 2048 x 16B per stage, 8 per thread, swizzled store
    auto fill = [&](int st, int kc) {
        uint32_t base = sbase + st * STAGE_BYTES;
        int k0 = kc * BK;
#pragma unroll
        for (int it = 0; it < 8; it++) {
            int q = tid + 256 * it;
            int plane = q >> 9;                  // 0=Ahi 1=Alo 2=Bhi 3=Blo
            int rr = (q >> 2) & 127;
            int cc = q & 3;
            uint32_t dst = base + plane * 8192 + rr * 64 + (((cc ^ ((rr >> 1) & 3))) << 4);
            const __nv_bfloat16* src;
            if      (plane == 0) src = Ah + (size_t)(row0 + rr) * KDIM + k0 + cc * 8;
            else if (plane == 1) src = Al + (size_t)(row0 + rr) * KDIM + k0 + cc * 8;
            else if (plane == 2) src = Bh + (size_t)(ybase + rr) * KDIM + k0 + cc * 8;
            else                 src = Bl + (size_t)(ybase + rr) * KDIM + k0 + cc * 8;
            CP_ASYNC16(dst, src);
        }
    };

    fill(0, 0); CP_COMMIT();
    fill(1, 1); CP_COMMIT();

    for (int kc = 0; kc < NCH; kc++) {
        CP_WAIT1();
        __syncthreads();                         // single barrier per chunk
        if (kc + 2 < NCH) fill((kc + 2) % NSTAGE, kc + 2);
        CP_COMMIT();

        uint32_t stg = sbase + (kc % NSTAGE) * STAGE_BYTES;
#pragma unroll
        for (int kk = 0; kk < 2; kk++) {
            uint32_t achunk = (uint32_t)((xa ^ (kk << 1)) << 4);
            uint32_t bchunk = (uint32_t)((xb ^ (kk << 1)) << 4);
            uint32_t ah[4][4], al[4][4], bh[4][2], bl[4][2];
#pragma unroll
            for (int i = 0; i < 4; i++) {
                uint32_t a_addr = stg + abase + i * 1024 + achunk;
                ldsm_x4(ah[i][0], ah[i][1], ah[i][2], ah[i][3], a_addr);
                ldsm_x4(al[i][0], al[i][1], al[i][2], al[i][3], a_addr + APLANE);
            }
#pragma unroll
            for (int jp = 0; jp < 2; jp++) {
                uint32_t b_addr = stg + 2 * APLANE + bbase + jp * 1024 + bchunk;
                ldsm_x4(bh[jp * 2][0], bh[jp * 2][1], bh[jp * 2 + 1][0], bh[jp * 2 + 1][1], b_addr);
                ldsm_x4(bl[jp * 2][0], bl[jp * 2][1], bl[jp * 2 + 1][0], bl[jp * 2 + 1][1],
                        b_addr + BPLANE);
            }
            // three independent passes: hh, hl, lh
#pragma unroll
            for (int i = 0; i < 4; i++)
#pragma unroll
                for (int j = 0; j < 4; j++) mma_bf16(c[i][j], ah[i], bh[j]);
#pragma unroll
            for (int i = 0; i < 4; i++)
#pragma unroll
                for (int j = 0; j < 4; j++) mma_bf16(c[i][j], ah[i], bl[j]);
#pragma unroll
            for (int i = 0; i < 4; i++)
#pragma unroll
                for (int j = 0; j < 4; j++) mma_bf16(c[i][j], al[i], bh[j]);
        }
        // no trailing barrier: next chunk's fill targets a stage whose reads
        // finished before the barrier at the top of the next iteration
    }

    // epilogue
#pragma unroll
    for (int i = 0; i < 4; i++) {
        int mr0 = wr * 64 + i * 16 + gid;
        int mr1 = mr0 + 8;
        if (FFN1) {
#pragma unroll
            for (int j = 0; j < 4; j++) {
                int col = wc * 32 + j * 8 + tig * 2;
                float u0 = gelu_exact(c[i][j][0]), u1 = gelu_exact(c[i][j][1]);
                float u2 = gelu_exact(c[i][j][2]), u3 = gelu_exact(c[i][j][3]);
                size_t i0 = (size_t)(row0 + mr0) * DFFN + n0 + col;
                size_t i1 = (size_t)(row0 + mr1) * DFFN + n0 + col;
                __nv_bfloat162 h0 = __floats2bfloat162_rn(u0, u1);
                float2 f0 = __bfloat1622float2(h0);
                *(__nv_bfloat162*)(g_h_hi + i0) = h0;
                *(__nv_bfloat162*)(g_h_lo + i0) = __floats2bfloat162_rn(u0 - f0.x, u1 - f0.y);
                __nv_bfloat162 h1 = __floats2bfloat162_rn(u2, u3);
                float2 f1 = __bfloat1622float2(h1);
                *(__nv_bfloat162*)(g_h_hi + i1) = h1;
                *(__nv_bfloat162*)(g_h_lo + i1) = __floats2bfloat162_rn(u2 - f1.x, u3 - f1.y);
            }
        } else {
            float ws0 = swt[mr0], ws1 = swt[mr1];
            float* y0 = g_y + (size_t)(row0 + mr0) * DMODEL + n0;
            float* y1 = g_y + (size_t)(row0 + mr1) * DMODEL + n0;
#pragma unroll
            for (int j = 0; j < 4; j++) {
                int col = wc * 32 + j * 8 + tig * 2;
                *(float2*)(y0 + col) = make_float2(ws0 * c[i][j][0], ws0 * c[i][j][1]);
                *(float2*)(y1 + col) = make_float2(ws1 * c[i][j][2], ws1 * c[i][j][3]);
            }
        }
    }
}

// ---------------- combine ----------------
__global__ __launch_bounds__(128) void combine_kernel(float* __restrict__ out) {
    int t = blockIdx.x;
    int ra = g_tok2row[t * 2 + 0];
    int rb = g_tok2row[t * 2 + 1];
    const float4* ya = (const float4*)(g_y + (size_t)ra * DMODEL);
    const float4* yb = (const float4*)(g_y + (size_t)rb * DMODEL);
    float4* o = (float4*)(out + (size_t)t * DMODEL);
    for (int i = threadIdx.x; i < DMODEL / 4; i += 128) {
        float4 a = ya[i], b = yb[i];
        o[i] = make_float4(a.x + b.x, a.y + b.y, a.z + b.z, a.w + b.w);
    }
}

// ---------------- aux losses ----------------
__global__ __launch_bounds__(256) void reduce_kernel(float* __restrict__ out, int out_size) {
    __shared__ float sbuf[256];
    int tid = threadIdx.x;

    float z = 0.f;
    for (int t = tid; t < TOKENS; t += 256) z += g_zsq[t];
    sbuf[tid] = z; __syncthreads();
    for (int s = 128; s; s >>= 1) { if (tid < s) sbuf[tid] += sbuf[tid + s]; __syncthreads(); }
    float zloss = sbuf[0] / (float)TOKENS;
    __syncthreads();

    float p[NEXP];
#pragma unroll
    for (int e = 0; e < NEXP; e++) p[e] = 0.f;
    for (int t = tid; t < TOKENS; t += 256) {
#pragma unroll
        for (int e = 0; e < NEXP; e++) p[e] += g_probs[t * NEXP + e];
    }
    float pi[NEXP];
#pragma unroll
    for (int e = 0; e < NEXP; e++) {
        sbuf[tid] = p[e]; __syncthreads();
        for (int s = 128; s; s >>= 1) { if (tid < s) sbuf[tid] += sbuf[tid + s]; __syncthreads(); }
        pi[e] = sbuf[0] / (float)TOKENS;
        __syncthreads();
    }

    if (tid == 0 && out_size >= TOKENS * DMODEL + 2 + NEXP) {
        float* tail = out + (size_t)TOKENS * DMODEL;
        tail[0] = zloss;
        float lb = 0.f;
#pragma unroll
        for (int e = 0; e < NEXP; e++) {
            float fi = (float)g_cnt[e] / (float)(TOKENS * TOPK);
            lb += fi * pi[e];
            tail[2 + e] = fi;
        }
        tail[1] = (float)NEXP * lb;
    }
}

// ---------------- host ----------------
extern "C" void kernel_launch(void* const* d_in, const int* in_sizes, int n_in,
                              void* d_out, int out_size) {
    const float* x  = (const float*)d_in[0];
    const float* rw = (const float*)d_in[1];
    const float* w1 = (const float*)d_in[2];
    const float* w2 = (const float*)d_in[3];
    float* out = (float*)d_out;

    void *p_cnt, *p_cur;
    void *p_xh, *p_xl, *p_hh, *p_hl, *p_w1h, *p_w1l, *p_w2h, *p_w2l;
    cudaGetSymbolAddress(&p_cnt, g_cnt);
    cudaGetSymbolAddress(&p_cur, g_cursor);
    cudaGetSymbolAddress(&p_xh,  g_xg_hi);
    cudaGetSymbolAddress(&p_xl,  g_xg_lo);
    cudaGetSymbolAddress(&p_hh,  g_h_hi);
    cudaGetSymbolAddress(&p_hl,  g_h_lo);
    cudaGetSymbolAddress(&p_w1h, g_w1t_hi);
    cudaGetSymbolAddress(&p_w1l, g_w1t_lo);
    cudaGetSymbolAddress(&p_w2h, g_w2t_hi);
    cudaGetSymbolAddress(&p_w2l, g_w2t_lo);

    cudaFuncSetAttribute(gemm_bf16<true>,  cudaFuncAttributeMaxDynamicSharedMemorySize, SMEM_SZ);
    cudaFuncSetAttribute(gemm_bf16<false>, cudaFuncAttributeMaxDynamicSharedMemorySize, SMEM_SZ);

    cudaMemsetAsync(p_cnt, 0, NEXP * sizeof(int));
    cudaMemsetAsync(p_cur, 0, NEXP * sizeof(int));

    // kernel launch order: gemm_bf16<true> is the 4th kernel (ncu capture slot)
    transpose_w1_split<<<dim3(16384 / 32, 1024 / 32), dim3(32, 8)>>>(w1);      // k1
    router_kernel<<<TOKENS / 8, 256>>>(x, rw);                                 // k2
    scatter_gather<<<TOKENS, 128>>>(x);                                        // k3

    gemm_bf16<true><<<dim3(DFFN / BN, ROW_TILES), 256, SMEM_SZ>>>(             // k4 <- profiled
        (const __nv_bfloat16*)p_xh, (const __nv_bfloat16*)p_xl,
        (const __nv_bfloat16*)p_w1h, (const __nv_bfloat16*)p_w1l);

    transpose_w2_split<<<dim3(1024 / 32, 2048 / 32, NEXP), dim3(32, 8)>>>(w2); // k5

    gemm_bf16<false><<<dim3(DMODEL / BN, ROW_TILES), 256, SMEM_SZ>>>(          // k6
        (const __nv_bfloat16*)p_hh, (const __nv_bfloat16*)p_hl,
        (const __nv_bfloat16*)p_w2h, (const __nv_bfloat16*)p_w2l);

    combine_kernel<<<TOKENS, 128>>>(out);                                      // k7
    reduce_kernel<<<1, 256>>>(out, out_size);                                  // k8
}